// round 17
// baseline (speedup 1.0000x reference)
#include <cuda_runtime.h>
#include <cuda_fp16.h>
#include <cstdint>

#define MAXN 100000
#define MAXE 1600000
#define D    128
#define G    64
#define REP  32
#define SCB  1024
#define TM   64      // nodes per fused-kernel block
#define PADH 136     // At pitch in halves: 272B -> 4-bank row shift, ldmatrix conflict-free

// ---------------- device scratch ----------------
__device__ __half g_xh[MAXN * D];       // fp16 pre-scaled input: dis_i * x_i
__device__ __half g_h2[MAXN * D];       // fp16 pre-scaled layer-1 activation
__device__ uint2  g_whf[2 * 4096];      // fp16 W1/W2 in m16n8k16 B-fragment order
__device__ int    g_deg[MAXN];
__device__ float  g_dis[MAXN];
__device__ int    g_off[MAXN + 1];
__device__ int    g_cursor[MAXN];
__device__ int    g_adj[MAXE];
__device__ float  g_gsum[G * REP];
__device__ int    g_bsum[128];
__device__ int    g_is64;

// ---------------- dtype-agnostic index read ----------------
__device__ __forceinline__ int idx_at(const void* p, size_t i, int is64) {
    if (is64) return (int)((const long long*)p)[i];
    return ((const int*)p)[i];
}

__device__ __forceinline__ int detect64(const int* w) {
    int allz = 1;
    for (int j = 1; j < 32; j += 2)
        if (w[j] != 0) allz = 0;
    return allz;
}

// ---------------- W prep: fp16 + permute to m16n8k16 B-fragment order ----------------
__global__ void k_wprep(const float* __restrict__ W1, const float* __restrict__ W2) {
    int i = blockIdx.x * blockDim.x + threadIdx.x;   // 0..8191
    int l = i >> 12;
    int r = i & 4095;
    int lane = r & 31;
    int nt = (r >> 5) & 15;
    int ks = r >> 9;
    int g = lane >> 2, tig = lane & 3;
    const float* W = l ? W2 : W1;
    int nn = nt * 8 + g;
    int k0 = ks * 16 + 2 * tig;
    __half2 x = __floats2half2_rn(W[k0 * D + nn], W[(k0 + 1) * D + nn]);
    __half2 y = __floats2half2_rn(W[(k0 + 8) * D + nn], W[(k0 + 9) * D + nn]);
    uint2 o;
    o.x = *(unsigned*)&x;
    o.y = *(unsigned*)&y;
    g_whf[i] = o;
}

// ---------------- in-degree count: 4 edges/thread (MLP 4) ----------------
__global__ void k_deg(const void* __restrict__ ei, int e) {
    __shared__ int s64;
    if (threadIdx.x == 0) s64 = detect64((const int*)ei);
    __syncthreads();
    int base = (blockIdx.x * blockDim.x + threadIdx.x) * 4;
    if (base + 4 <= e) {
        int c0 = idx_at(ei, (size_t)e + base + 0, s64);
        int c1 = idx_at(ei, (size_t)e + base + 1, s64);
        int c2 = idx_at(ei, (size_t)e + base + 2, s64);
        int c3 = idx_at(ei, (size_t)e + base + 3, s64);
        atomicAdd(&g_deg[c0], 1);
        atomicAdd(&g_deg[c1], 1);
        atomicAdd(&g_deg[c2], 1);
        atomicAdd(&g_deg[c3], 1);
    } else {
        for (int i = base; i < e; i++)
            atomicAdd(&g_deg[idx_at(ei, (size_t)e + i, s64)], 1);
    }
}

// ---------------- scanA: block sums of deg; dis=rsqrt(deg+1); publish g_is64 ----------------
__global__ void k_scanA(const int* __restrict__ ei32, int n) {
    if (blockIdx.x == 0 && threadIdx.x == 0) g_is64 = detect64(ei32);
    int i = blockIdx.x * SCB + threadIdx.x;
    int v = 0;
    if (i < n) {
        int d = g_deg[i];
        g_dis[i] = rsqrtf((float)(d + 1));
        v = d;
    }
    int s = v;
#pragma unroll
    for (int o = 16; o; o >>= 1) s += __shfl_down_sync(0xffffffffu, s, o);
    __shared__ int ws[SCB / 32];
    int w = threadIdx.x >> 5, l = threadIdx.x & 31;
    if (l == 0) ws[w] = s;
    __syncthreads();
    if (w == 0) {
        int t = (l < SCB / 32) ? ws[l] : 0;
#pragma unroll
        for (int o = 16; o; o >>= 1) t += __shfl_down_sync(0xffffffffu, t, o);
        if (l == 0) g_bsum[blockIdx.x] = t;
    }
}

// ---------------- prescale: xh = fp16(dis .* x)  (forked stream) ----------------
__global__ void k_prescale(const float4* __restrict__ x, uint2* __restrict__ xh, int n4) {
    int i = blockIdx.x * blockDim.x + threadIdx.x;
    if (i < n4) {
        float d = g_dis[i >> 5];
        float4 v = x[i];
        __half2 h0 = __floats2half2_rn(v.x * d, v.y * d);
        __half2 h1 = __floats2half2_rn(v.z * d, v.w * d);
        uint2 o;
        o.x = *(unsigned*)&h0;
        o.y = *(unsigned*)&h1;
        xh[i] = o;
    }
}

// ---------------- scanB: redundant block-sum scan + offsets + cursor ----------------
__global__ void k_scanB(int nb, int n) {
    __shared__ int sm[128];
    __shared__ int ws[SCB / 32];
    int t = threadIdx.x;
    if (t < 128) sm[t] = (t < nb) ? g_bsum[t] : 0;
    __syncthreads();
    for (int o = 1; o < 128; o <<= 1) {
        int u = (t >= o && t < 128) ? sm[t - o] : 0;
        __syncthreads();
        if (t >= o && t < 128) sm[t] += u;
        __syncthreads();
    }
    int bbase = sm[blockIdx.x] - g_bsum[blockIdx.x];
    if (blockIdx.x == 0 && t == 0) g_off[n] = sm[127];

    int i = blockIdx.x * SCB + t;
    int v = (i < n) ? g_deg[i] : 0;
    int incl = v;
#pragma unroll
    for (int o = 1; o < 32; o <<= 1) {
        int u = __shfl_up_sync(0xffffffffu, incl, o);
        if ((t & 31) >= o) incl += u;
    }
    int w = t >> 5, l = t & 31;
    if (l == 31) ws[w] = incl;
    __syncthreads();
    if (w == 0) {
        int s = (l < SCB / 32) ? ws[l] : 0;
        int si = s;
#pragma unroll
        for (int o = 1; o < 32; o <<= 1) {
            int u = __shfl_up_sync(0xffffffffu, si, o);
            if (l >= o) si += u;
        }
        ws[l] = si - s;
    }
    __syncthreads();
    if (i < n) {
        int off = bbase + ws[w] + (incl - v);
        g_off[i] = off;
        g_cursor[i] = off;
    }
}

// ---------------- fill CSR: 4 edges/thread (MLP 4) ----------------
__global__ void k_fill(const void* __restrict__ ei, int e) {
    int is64 = g_is64;
    int base = (blockIdx.x * blockDim.x + threadIdx.x) * 4;
    if (base + 4 <= e) {
        int r0 = idx_at(ei, base + 0, is64);
        int r1 = idx_at(ei, base + 1, is64);
        int r2 = idx_at(ei, base + 2, is64);
        int r3 = idx_at(ei, base + 3, is64);
        int c0 = idx_at(ei, (size_t)e + base + 0, is64);
        int c1 = idx_at(ei, (size_t)e + base + 1, is64);
        int c2 = idx_at(ei, (size_t)e + base + 2, is64);
        int c3 = idx_at(ei, (size_t)e + base + 3, is64);
        int p0 = atomicAdd(&g_cursor[c0], 1);
        int p1 = atomicAdd(&g_cursor[c1], 1);
        int p2 = atomicAdd(&g_cursor[c2], 1);
        int p3 = atomicAdd(&g_cursor[c3], 1);
        g_adj[p0] = r0;
        g_adj[p1] = r1;
        g_adj[p2] = r2;
        g_adj[p3] = r3;
    } else {
        for (int i = base; i < e; i++) {
            int r = idx_at(ei, i, is64);
            int c = idx_at(ei, (size_t)e + i, is64);
            int pos = atomicAdd(&g_cursor[c], 1);
            g_adj[pos] = r;
        }
    }
}

// ---------------- fused layer: fp16 gather -> smem -> HMMA tensor GEMM -> epilogue ----------------
__device__ __forceinline__ float leaky(float x) { return x >= 0.f ? x : 0.01f * x; }

template <int POOL>
__global__ __launch_bounds__(256, 4) void k_fused(
    const uint2* __restrict__ in, const uint2* __restrict__ whf,
    const float* __restrict__ bias, const float* __restrict__ fcW,
    const void* __restrict__ batch, void* __restrict__ hout, int n)
{
    __shared__ __half At[TM][PADH];     // node-major fp16 agg tile
    __shared__ float rowsum[TM];

    int tid = threadIdx.x;
    int warp = tid >> 5, lane = tid & 31;
    int row0 = blockIdx.x * TM;

    // ---- phase 1: gather (warp per node, lane = feature quad), 4-wide MLP ----
    for (int nd = warp; nd < TM; nd += 8) {
        int node = row0 + nd;
        float4 acc = make_float4(0.f, 0.f, 0.f, 0.f);
        if (node < n) {
            float di = g_dis[node];
            uint2 u = in[(size_t)node * 32 + lane];
            float2 f0 = __half22float2(*(const __half2*)&u.x);
            float2 f1 = __half22float2(*(const __half2*)&u.y);
            acc.x = f0.x; acc.y = f0.y; acc.z = f1.x; acc.w = f1.y;
            int s = g_off[node], e = g_off[node + 1];
            int j = s;
            for (; j + 4 <= e; j += 4) {
                int s0 = g_adj[j], s1 = g_adj[j + 1], s2 = g_adj[j + 2], s3 = g_adj[j + 3];
                uint2 u0 = in[(size_t)s0 * 32 + lane];
                uint2 u1 = in[(size_t)s1 * 32 + lane];
                uint2 u2 = in[(size_t)s2 * 32 + lane];
                uint2 u3 = in[(size_t)s3 * 32 + lane];
                float2 a0 = __half22float2(*(const __half2*)&u0.x);
                float2 b0 = __half22float2(*(const __half2*)&u0.y);
                float2 a1 = __half22float2(*(const __half2*)&u1.x);
                float2 b1 = __half22float2(*(const __half2*)&u1.y);
                float2 a2 = __half22float2(*(const __half2*)&u2.x);
                float2 b2 = __half22float2(*(const __half2*)&u2.y);
                float2 a3 = __half22float2(*(const __half2*)&u3.x);
                float2 b3 = __half22float2(*(const __half2*)&u3.y);
                acc.x += a0.x + a1.x + a2.x + a3.x;
                acc.y += a0.y + a1.y + a2.y + a3.y;
                acc.z += b0.x + b1.x + b2.x + b3.x;
                acc.w += b0.y + b1.y + b2.y + b3.y;
            }
            for (; j < e; j++) {
                int s0 = g_adj[j];
                uint2 u0 = in[(size_t)s0 * 32 + lane];
                float2 a0 = __half22float2(*(const __half2*)&u0.x);
                float2 b0 = __half22float2(*(const __half2*)&u0.y);
                acc.x += a0.x; acc.y += a0.y; acc.z += b0.x; acc.w += b0.y;
            }
            acc.x *= di; acc.y *= di; acc.z *= di; acc.w *= di;
        }
        __half2 h0 = __floats2half2_rn(acc.x, acc.y);
        __half2 h1 = __floats2half2_rn(acc.z, acc.w);
        uint2 st;
        st.x = *(unsigned*)&h0;
        st.y = *(unsigned*)&h1;
        *(uint2*)&At[nd][lane * 4] = st;
    }
    if (POOL && tid < TM) rowsum[tid] = 0.f;
    __syncthreads();

    // ---- phase 2: tensor-core GEMM C[64x128] = At @ W (m16n8k16 fp16, fp32 accum) ----
    int g = lane >> 2, tig = lane & 3;
    int m0 = (warp & 3) * 16;           // 16-node strip
    int nb0 = (warp >> 2) * 8;          // 8 n-tiles (64 cols)
    uint32_t at_base = (uint32_t)__cvta_generic_to_shared(&At[0][0]);
    int tt = lane >> 3, rr = lane & 7;
    uint32_t arow = at_base +
        (uint32_t)(((m0 + (tt & 1) * 8 + rr) * PADH + (tt >> 1) * 8) * 2);

    float c[8][4];
#pragma unroll
    for (int nt = 0; nt < 8; nt++)
#pragma unroll
        for (int q = 0; q < 4; q++) c[nt][q] = 0.f;

#pragma unroll
    for (int ks = 0; ks < 8; ks++) {
        uint32_t a0, a1, a2, a3;
        asm volatile(
            "ldmatrix.sync.aligned.m8n8.x4.shared.b16 {%0,%1,%2,%3}, [%4];"
            : "=r"(a0), "=r"(a1), "=r"(a2), "=r"(a3)
            : "r"(arow + (uint32_t)(ks * 32)));
#pragma unroll
        for (int nt = 0; nt < 8; nt++) {
            uint2 b = __ldg(&whf[(ks * 16 + nb0 + nt) * 32 + lane]);
            asm volatile(
                "mma.sync.aligned.m16n8k16.row.col.f32.f16.f16.f32 "
                "{%0,%1,%2,%3}, {%4,%5,%6,%7}, {%8,%9}, {%0,%1,%2,%3};"
                : "+f"(c[nt][0]), "+f"(c[nt][1]), "+f"(c[nt][2]), "+f"(c[nt][3])
                : "r"(a0), "r"(a1), "r"(a2), "r"(a3), "r"(b.x), "r"(b.y));
        }
    }

    // ---- phase 3: epilogue ----
    int r0g = row0 + m0 + g;
    int r1g = r0g + 8;
    if (!POOL) {
        __half* hh = (__half*)hout;
        float d0 = (r0g < n) ? g_dis[r0g] : 0.f;
        float d1 = (r1g < n) ? g_dis[r1g] : 0.f;
#pragma unroll
        for (int nt = 0; nt < 8; nt++) {
            int col = (nb0 + nt) * 8 + 2 * tig;
            float b0 = bias[col], b1 = bias[col + 1];
            if (r0g < n) {
                __half2 h = __floats2half2_rn(d0 * leaky(c[nt][0] + b0),
                                              d0 * leaky(c[nt][1] + b1));
                *(__half2*)&hh[(size_t)r0g * D + col] = h;
            }
            if (r1g < n) {
                __half2 h = __floats2half2_rn(d1 * leaky(c[nt][2] + b0),
                                              d1 * leaky(c[nt][3] + b1));
                *(__half2*)&hh[(size_t)r1g * D + col] = h;
            }
        }
    } else {
        float p0 = 0.f, p1 = 0.f;
#pragma unroll
        for (int nt = 0; nt < 8; nt++) {
            int col = (nb0 + nt) * 8 + 2 * tig;
            float b0 = bias[col], b1 = bias[col + 1];
            float f0 = fcW[col], f1 = fcW[col + 1];
            p0 += leaky(c[nt][0] + b0) * f0 + leaky(c[nt][1] + b1) * f1;
            p1 += leaky(c[nt][2] + b0) * f0 + leaky(c[nt][3] + b1) * f1;
        }
        p0 += __shfl_xor_sync(0xffffffffu, p0, 1);
        p0 += __shfl_xor_sync(0xffffffffu, p0, 2);
        p1 += __shfl_xor_sync(0xffffffffu, p1, 1);
        p1 += __shfl_xor_sync(0xffffffffu, p1, 2);
        if (tig == 0) {
            atomicAdd(&rowsum[m0 + g], p0);
            atomicAdd(&rowsum[m0 + g + 8], p1);
        }
        __syncthreads();
        if (tid < TM) {
            int row = row0 + tid;
            if (row < n) {
                int gg = idx_at(batch, row, g_is64);
                atomicAdd(&g_gsum[gg * REP + (blockIdx.x & (REP - 1))], rowsum[tid]);
            }
        }
    }
}

// ---------------- final ----------------
__global__ void k_final(const void* __restrict__ batch, const float* __restrict__ fcb,
                        float* __restrict__ out, int n) {
    __shared__ int lb[G + 1];
    int is64 = g_is64;
    int t = threadIdx.x;
    if (t <= G) {
        int lo = 0, hi = n;
        while (lo < hi) {
            int mid = (lo + hi) >> 1;
            if (idx_at(batch, mid, is64) < t) lo = mid + 1; else hi = mid;
        }
        lb[t] = lo;
    }
    __syncthreads();
    if (t < G) {
        float s = 0.f;
#pragma unroll
        for (int r = 0; r < REP; r++) s += g_gsum[t * REP + r];
        float c = (float)(lb[t + 1] - lb[t]);
        if (c < 1.f) c = 1.f;
        out[t] = s / c + fcb[0];
    }
}

// ---------------- launch ----------------
extern "C" void kernel_launch(void* const* d_in, const int* in_sizes, int n_in,
                              void* d_out, int out_size) {
    const float* x    = (const float*)d_in[0];
    const void*  ei   = d_in[1];
    const void*  bat  = d_in[2];
    const float* W1   = (const float*)d_in[3];
    const float* b1   = (const float*)d_in[4];
    const float* W2   = (const float*)d_in[5];
    const float* b2   = (const float*)d_in[6];
    const float* fcW  = (const float*)d_in[7];
    const float* fcb  = (const float*)d_in[8];
    float*       out  = (float*)d_out;

    int n = in_sizes[0] / D;
    int e = in_sizes[1] / 2;
    int nb = (n + SCB - 1) / SCB;

    void *xh, *h2, *whf, *degp, *gsump;
    cudaGetSymbolAddress(&xh, g_xh);
    cudaGetSymbolAddress(&h2, g_h2);
    cudaGetSymbolAddress(&whf, g_whf);
    cudaGetSymbolAddress(&degp, g_deg);
    cudaGetSymbolAddress(&gsump, g_gsum);

    static cudaStream_t s2 = nullptr;
    static cudaEvent_t ev_dis = nullptr, ev_xh = nullptr;
    if (!s2) {
        cudaStreamCreateWithFlags(&s2, cudaStreamNonBlocking);
        cudaEventCreateWithFlags(&ev_dis, cudaEventDisableTiming);
        cudaEventCreateWithFlags(&ev_xh, cudaEventDisableTiming);
    }

    int tb = 256;
    // fork stream: W fragment prep (independent of CSR)
    k_wprep<<<32, 256, 0, s2>>>(W1, W2);

    // CSR build on main stream
    cudaMemsetAsync(degp, 0, (size_t)n * sizeof(int), 0);
    cudaMemsetAsync(gsump, 0, (size_t)G * REP * sizeof(float), 0);
    int e4 = (e + 3) / 4;
    k_deg<<<(e4 + tb - 1) / tb, tb>>>(ei, e);
    k_scanA<<<nb, SCB>>>((const int*)ei, n);
    cudaEventRecord(ev_dis, 0);

    // fork: prescale xh = fp16(dis .* x), overlaps scanB + fill
    cudaStreamWaitEvent(s2, ev_dis, 0);
    int n4 = n * 32;
    k_prescale<<<(n4 + tb - 1) / tb, tb, 0, s2>>>((const float4*)x, (uint2*)xh, n4);
    cudaEventRecord(ev_xh, s2);

    k_scanB<<<nb, SCB>>>(nb, n);
    k_fill<<<(e4 + tb - 1) / tb, tb>>>(ei, e);

    cudaStreamWaitEvent(0, ev_xh, 0);
    int gblk = (n + TM - 1) / TM;
    // layer 1: h2(fp16) = dis .* leaky(dis.*(sum xh)@W1 + b1)
    k_fused<0><<<gblk, 256>>>((const uint2*)xh, (const uint2*)whf, b1, nullptr,
                              nullptr, h2, n);
    // layer 2 + pool/fc
    k_fused<1><<<gblk, 256>>>((const uint2*)h2, (const uint2*)whf + 4096, b2, fcW,
                              bat, nullptr, n);

    k_final<<<1, 128>>>(bat, fcb, out, n);
}